// round 10
// baseline (speedup 1.0000x reference)
#include <cuda_runtime.h>

// Problem constants (fixed by the reference)
#define HH   352
#define WW   1216
#define BB   2
#define PP   65536
#define CC   64
#define KTOP 8
#define SLOTS 16
#define HWPIX (HH*WW)          // 428032
#define NPIX  (BB*HWPIX)       // 856064

#define RR_F   ((float)((3.0/1216.0)*(3.0/1216.0)))   // r*r; also dist divisor (RAD_POW=2)
#define INVW2  ((float)(2.0/1216.0))
#define INVH2  ((float)(2.0/352.0))

// ---- scratch (allocation-free: __device__ globals, zero-initialized at load) ----
__device__ int                g_cnt[NPIX];             // self-cleaning (composite resets)
__device__ unsigned long long g_key[NPIX * SLOTS];     // (z_bits<<32) | pid
__device__ float              g_d2 [NPIX * SLOTS];
__device__ float              g_feats[BB * PP * CC];   // transposed features [B*P, C]

// ---------------------------------------------------------------------------
// Stage 1 (fused): blocks [0, SB) scatter points; blocks [SB, SB+TB) transpose.
// The two halves touch disjoint buffers, so no intra-kernel ordering is needed.
#define SB (BB * PP / 256)                   // 512 scatter blocks
#define TB ((PP / 32) * (CC / 32) * BB)      // 8192 transpose blocks

__global__ void __launch_bounds__(256) stage1_kernel(const float* __restrict__ pts,
                                                     const float* __restrict__ src) {
    int tx = threadIdx.x, ty = threadIdx.y;            // block (32,8)

    if (blockIdx.x < SB) {
        // ---- scatter: one thread per packed point id ----
        int pid = blockIdx.x * 256 + ty * 32 + tx;

        float x = pts[pid * 3 + 0];
        float y = pts[pid * 3 + 1];
        float z = pts[pid * 3 + 2];
        if (!(z > 0.0f)) return;

        int b  = pid >> 16;   // P = 65536
        int i0 = (int)floorf((y + 1.0f) * 0.5f * (float)HH);
        int j0 = (int)floorf((x + 1.0f) * 0.5f * (float)WW);

        unsigned long long kk =
            ((unsigned long long)__float_as_uint(z) << 32) | (unsigned int)pid;

        #pragma unroll
        for (int di = -1; di <= 1; di++) {
            int ii = i0 + di;
            if (ii < 0 || ii >= HH) continue;
            float yc = ((float)ii + 0.5f) * INVH2 - 1.0f;
            float dy = y - yc;
            float dy2 = dy * dy;
            #pragma unroll
            for (int dj = -2; dj <= 2; dj++) {
                int jj = j0 + dj;
                if (jj < 0 || jj >= WW) continue;
                float xc = ((float)jj + 0.5f) * INVW2 - 1.0f;
                float dx = x - xc;
                float d2 = dx * dx + dy2;
                if (d2 < RR_F) {
                    int pix = (b * HH + ii) * WW + jj;
                    int s = atomicAdd(&g_cnt[pix], 1);
                    if (s < SLOTS) {
                        g_key[pix * SLOTS + s] = kk;
                        g_d2 [pix * SLOTS + s] = d2;
                    }
                }
            }
        }
        return;
    }

    // ---- transpose: src [B, C, P] -> g_feats [B*P, C] ----
    int tb = blockIdx.x - SB;
    int pt = tb & 2047;            // P/32 = 2048
    int ct = (tb >> 11) & 1;       // C/32 = 2
    int b  = tb >> 12;

    __shared__ float tile[32][33];
    const float* s = src + ((size_t)b * CC + ct * 32) * PP + (size_t)pt * 32;
    #pragma unroll
    for (int i = 0; i < 32; i += 8)
        tile[ty + i][tx] = s[(size_t)(ty + i) * PP + tx];
    __syncthreads();
    float* d = g_feats + ((size_t)b * PP + pt * 32) * CC + ct * 32;
    #pragma unroll
    for (int i = 0; i < 32; i += 8)
        d[(size_t)(ty + i) * CC + tx] = tile[tx][ty + i];
}

// ---------------------------------------------------------------------------
// One thread per pixel. Top-8 retention insertion sort by (z, pid) key
// (== reference lexsort + rank<K). Accumulate 64 channels in 4 passes of 16
// to keep register pressure low. Resets g_cnt for the next graph replay.
__global__ void __launch_bounds__(256) composite_kernel(float* __restrict__ out) {
    int pix = blockIdx.x * blockDim.x + threadIdx.x;   // NPIX % 256 == 0

    int n = g_cnt[pix];
    g_cnt[pix] = 0;                 // self-clean for next replay
    if (n > SLOTS) n = SLOTS;

    unsigned long long key[KTOP];
    float dd[KTOP];
    int m = 0;
    int base = pix * SLOTS;
    for (int i = 0; i < n; i++) {
        unsigned long long k = g_key[base + i];
        float d = g_d2[base + i];
        if (m < KTOP) {
            int j = m++;
            while (j > 0 && key[j - 1] > k) {
                key[j] = key[j - 1]; dd[j] = dd[j - 1]; j--;
            }
            key[j] = k; dd[j] = d;
        } else if (k < key[KTOP - 1]) {
            int j = KTOP - 1;
            while (j > 0 && key[j - 1] > k) {
                key[j] = key[j - 1]; dd[j] = dd[j - 1]; j--;
            }
            key[j] = k; dd[j] = d;
        }
    }

    float w[KTOP];
    int   p[KTOP];
    for (int k = 0; k < m; k++) {
        float dist = dd[k] / RR_F;
        dist = fminf(fmaxf(dist, 0.001f), 1.0f);
        w[k] = 1.0f - sqrtf(dist);
        p[k] = (int)(unsigned int)(key[k] & 0xffffffffu);
    }

    int b   = pix / HWPIX;
    int rem = pix - b * HWPIX;
    float* o = out + (size_t)b * CC * HWPIX + rem;
    const float4* f4 = (const float4*)g_feats;

    #pragma unroll
    for (int cb = 0; cb < 4; cb++) {            // 4 passes x 16 channels
        float acc[16];
        #pragma unroll
        for (int c = 0; c < 16; c++) acc[c] = 0.0f;

        for (int k = 0; k < m; k++) {
            float wk = w[k];
            const float4* row = f4 + (size_t)p[k] * (CC / 4) + cb * 4;
            #pragma unroll
            for (int j = 0; j < 4; j++) {
                float4 f = row[j];
                acc[4 * j + 0] += wk * f.x;
                acc[4 * j + 1] += wk * f.y;
                acc[4 * j + 2] += wk * f.z;
                acc[4 * j + 3] += wk * f.w;
            }
        }

        #pragma unroll
        for (int c = 0; c < 16; c++)
            o[(size_t)(cb * 16 + c) * HWPIX] = acc[c];
    }
}

// ---------------------------------------------------------------------------
extern "C" void kernel_launch(void* const* d_in, const int* in_sizes, int n_in,
                              void* d_out, int out_size) {
    const float* pts = (const float*)d_in[0];  // [B, P, 3]
    const float* src = (const float*)d_in[1];  // [B, C, P]
    float* out = (float*)d_out;                // [B, C, H, W]

    {
        dim3 block(32, 8);
        stage1_kernel<<<SB + TB, block>>>(pts, src);
    }
    composite_kernel<<<NPIX / 256, 256>>>(out);
}

// round 11
// speedup vs baseline: 1.3821x; 1.3821x over previous
#include <cuda_runtime.h>

// Problem constants (fixed by the reference)
#define HH   352
#define WW   1216
#define BB   2
#define PP   65536
#define CC   64
#define KTOP 8
#define SLOTS 16
#define HWPIX (HH*WW)          // 428032
#define NPIX  (BB*HWPIX)       // 856064

#define RR_F    ((float)((3.0/1216.0)*(3.0/1216.0)))   // r*r; also dist divisor (RAD_POW=2)
#define INV_RR  ((float)(1.0/((3.0/1216.0)*(3.0/1216.0))))
#define INVW2   ((float)(2.0/1216.0))
#define INVH2   ((float)(2.0/352.0))

// ---- scratch (allocation-free: __device__ globals, zero-initialized at load) ----
__device__ int        g_cnt[NPIX];              // self-cleaning (composite resets)
__device__ ulonglong2 g_rec[NPIX * SLOTS];      // .x = (z_bits<<32)|pid, .y = d2 bits
__device__ float      g_feats[BB * PP * CC];    // transposed features [B*P, C]

// ---------------------------------------------------------------------------
// Stage 1 (fused): blocks [0, SB) scatter points; blocks [SB, SB+TB) transpose.
#define SB (BB * PP / 256)                   // 512 scatter blocks
#define TB ((PP / 32) * (CC / 32) * BB)      // 8192 transpose blocks

__global__ void __launch_bounds__(256) stage1_kernel(const float* __restrict__ pts,
                                                     const float* __restrict__ src) {
    int tx = threadIdx.x, ty = threadIdx.y;            // block (32,8)

    if (blockIdx.x < SB) {
        // ---- scatter: one thread per packed point id ----
        int pid = blockIdx.x * 256 + ty * 32 + tx;

        float x = pts[pid * 3 + 0];
        float y = pts[pid * 3 + 1];
        float z = pts[pid * 3 + 2];
        if (!(z > 0.0f)) return;

        int b  = pid >> 16;   // P = 65536
        int i0 = (int)floorf((y + 1.0f) * 0.5f * (float)HH);
        int j0 = (int)floorf((x + 1.0f) * 0.5f * (float)WW);

        unsigned long long kk =
            ((unsigned long long)__float_as_uint(z) << 32) | (unsigned int)pid;

        #pragma unroll
        for (int di = -1; di <= 1; di++) {
            int ii = i0 + di;
            if (ii < 0 || ii >= HH) continue;
            float yc = ((float)ii + 0.5f) * INVH2 - 1.0f;
            float dy = y - yc;
            float dy2 = dy * dy;
            #pragma unroll
            for (int dj = -2; dj <= 2; dj++) {
                int jj = j0 + dj;
                if (jj < 0 || jj >= WW) continue;
                float xc = ((float)jj + 0.5f) * INVW2 - 1.0f;
                float dx = x - xc;
                float d2 = dx * dx + dy2;
                if (d2 < RR_F) {
                    int pix = (b * HH + ii) * WW + jj;
                    int s = atomicAdd(&g_cnt[pix], 1);
                    if (s < SLOTS) {
                        ulonglong2 rec;
                        rec.x = kk;
                        rec.y = (unsigned long long)__float_as_uint(d2);
                        g_rec[pix * SLOTS + s] = rec;
                    }
                }
            }
        }
        return;
    }

    // ---- transpose: src [B, C, P] -> g_feats [B*P, C] ----
    int tb = blockIdx.x - SB;
    int pt = tb & 2047;            // P/32 = 2048
    int ct = (tb >> 11) & 1;       // C/32 = 2
    int b  = tb >> 12;

    __shared__ float tile[32][33];
    const float* s = src + ((size_t)b * CC + ct * 32) * PP + (size_t)pt * 32;
    #pragma unroll
    for (int i = 0; i < 32; i += 8)
        tile[ty + i][tx] = s[(size_t)(ty + i) * PP + tx];
    __syncthreads();
    float* d = g_feats + ((size_t)b * PP + pt * 32) * CC + ct * 32;
    #pragma unroll
    for (int i = 0; i < 32; i += 8)
        d[(size_t)(ty + i) * CC + tx] = tile[tx][ty + i];
}

// ---------------------------------------------------------------------------
// Block (128,2): 2 threads per pixel, 32 channels each. No sort: with
// lambda~1.08 candidates/pixel, n<=8 covers all but ~1e-6 of pixels, and the
// top-8 SET (not order) is all that affects the result beyond FP rounding.
// Slow path (n>8): repeated min-scan by unique (z,pid) key.
__global__ void __launch_bounds__(256) composite_kernel(float* __restrict__ out) {
    int tx   = threadIdx.x;          // pixel within block
    int half = threadIdx.y;          // channel half (0: c0-31, 1: c32-63)
    int pix  = blockIdx.x * 128 + tx;    // NPIX % 128 == 0

    int n = g_cnt[pix];
    __syncthreads();                 // both halves read n before the reset
    if (half == 0) g_cnt[pix] = 0;   // self-clean for next graph replay
    if (n > SLOTS) n = SLOTS;

    float acc[32];
    #pragma unroll
    for (int c = 0; c < 32; c++) acc[c] = 0.0f;

    const float4* f4 = (const float4*)g_feats;
    const ulonglong2* rec = g_rec + pix * SLOTS;

    if (n <= KTOP) {
        // fast path: all candidates kept
        for (int i = 0; i < n; i++) {
            ulonglong2 r = rec[i];
            float d2v  = __uint_as_float((unsigned int)r.y);
            float dist = fminf(fmaxf(d2v * INV_RR, 0.001f), 1.0f);
            float wk   = 1.0f - sqrtf(dist);
            int   p    = (int)(unsigned int)(r.x & 0xffffffffu);
            const float4* row = f4 + (size_t)p * (CC / 4) + half * 8;
            #pragma unroll
            for (int j = 0; j < 8; j++) {
                float4 f = row[j];
                acc[4 * j + 0] += wk * f.x;
                acc[4 * j + 1] += wk * f.y;
                acc[4 * j + 2] += wk * f.z;
                acc[4 * j + 3] += wk * f.w;
            }
        }
    } else {
        // rare path (~1e-6 of pixels): pick 8 smallest unique keys
        unsigned long long prev = 0ull;   // z>0 => key >= 2^32 > 0
        for (int sel = 0; sel < KTOP; sel++) {
            unsigned long long best = ~0ull;
            float bd = 0.0f;
            for (int i = 0; i < n; i++) {
                ulonglong2 r = rec[i];
                if (r.x > prev && r.x < best) {
                    best = r.x;
                    bd = __uint_as_float((unsigned int)r.y);
                }
            }
            prev = best;
            float dist = fminf(fmaxf(bd * INV_RR, 0.001f), 1.0f);
            float wk   = 1.0f - sqrtf(dist);
            int   p    = (int)(unsigned int)(best & 0xffffffffu);
            const float4* row = f4 + (size_t)p * (CC / 4) + half * 8;
            #pragma unroll
            for (int j = 0; j < 8; j++) {
                float4 f = row[j];
                acc[4 * j + 0] += wk * f.x;
                acc[4 * j + 1] += wk * f.y;
                acc[4 * j + 2] += wk * f.z;
                acc[4 * j + 3] += wk * f.w;
            }
        }
    }

    int b   = pix / HWPIX;
    int rem = pix - b * HWPIX;
    float* o = out + (size_t)b * CC * HWPIX + (size_t)(half * 32) * HWPIX + rem;
    #pragma unroll
    for (int c = 0; c < 32; c++)
        o[(size_t)c * HWPIX] = acc[c];
}

// ---------------------------------------------------------------------------
extern "C" void kernel_launch(void* const* d_in, const int* in_sizes, int n_in,
                              void* d_out, int out_size) {
    const float* pts = (const float*)d_in[0];  // [B, P, 3]
    const float* src = (const float*)d_in[1];  // [B, C, P]
    float* out = (float*)d_out;                // [B, C, H, W]

    {
        dim3 block(32, 8);
        stage1_kernel<<<SB + TB, block>>>(pts, src);
    }
    {
        dim3 block(128, 2);
        composite_kernel<<<NPIX / 128, block>>>(out);
    }
}